// round 15
// baseline (speedup 1.0000x reference)
#include <cuda_runtime.h>
#include <cuda_bf16.h>
#include <cuda_fp16.h>
#include <cstdint>

#define SEQ  2048
#define HID  5120
#define QKVN 15360

// ---------------- scratch (device globals; allocation-free) ----------------
__device__ __align__(256) __half g_qk_h[SEQ * QKVN];   // qkv fp16 (hi only)
__device__ __align__(256) __half g_hs_h[SEQ * HID];
__device__ __align__(256) __half g_wp_h[QKVN * HID];   // w_pack hi only
__device__ __align__(256) __half g_wo_h[HID * HID];    // w_o hi only
__device__ __align__(256) __half g_at_h[SEQ * HID];    // attn out fp16 (hi only)

// ---------------- helpers ----------------
__device__ __forceinline__ uint32_t cvta_s(const void* p) {
    return (uint32_t)__cvta_generic_to_shared(p);
}
__device__ __forceinline__ uint32_t pack2h(float f0, float f1) {
    __half2 v = __floats2half2_rn(f0, f1);
    return *reinterpret_cast<uint32_t*>(&v);
}
__device__ __forceinline__ void ldsm4(uint32_t r[4], uint32_t a) {
    asm volatile("ldmatrix.sync.aligned.m8n8.x4.shared.b16 {%0,%1,%2,%3}, [%4];"
                 : "=r"(r[0]), "=r"(r[1]), "=r"(r[2]), "=r"(r[3]) : "r"(a));
}
__device__ __forceinline__ void ldsm4t(uint32_t r[4], uint32_t a) {
    asm volatile("ldmatrix.sync.aligned.m8n8.x4.trans.shared.b16 {%0,%1,%2,%3}, [%4];"
                 : "=r"(r[0]), "=r"(r[1]), "=r"(r[2]), "=r"(r[3]) : "r"(a));
}
__device__ __forceinline__ void mma_f16(float d[4], const uint32_t a[4], const uint32_t b[2]) {
    asm volatile("mma.sync.aligned.m16n8k16.row.col.f32.f16.f16.f32 "
                 "{%0,%1,%2,%3}, {%4,%5,%6,%7}, {%8,%9}, {%0,%1,%2,%3};"
                 : "+f"(d[0]), "+f"(d[1]), "+f"(d[2]), "+f"(d[3])
                 : "r"(a[0]), "r"(a[1]), "r"(a[2]), "r"(a[3]), "r"(b[0]), "r"(b[1]));
}
__device__ __forceinline__ void cp16(uint32_t dst, const void* src) {
    asm volatile("cp.async.cg.shared.global [%0], [%1], 16;" :: "r"(dst), "l"(src));
}

// ---------------- prepass: fp32 -> fp16 ----------------
__global__ __launch_bounds__(256) void split_h16_kernel(const float4* __restrict__ src,
                                                        uint2* __restrict__ hi, int n4) {
    int i = blockIdx.x * blockDim.x + threadIdx.x;
    if (i >= n4) return;
    float4 v = src[i];
    hi[i] = make_uint2(pack2h(v.x, v.y), pack2h(v.z, v.w));
}

// ---------------- GEMM (fp16, 1-term): C = Ah * Bh^T ------------------------
// BM=128, BN=128, BK=64, 2 stages, 2 CTAs/SM. 8 warps 4(m)x2(n).
// HALF_OUT: write fp16 (Ch); else fp32 (C).
#define GPAD 72
#define HARR (128 * GPAD * 2)                 // 18432 B per array
#define HSTAGE (2 * HARR)                     // 36864
#define G1_SMEM (2 * HSTAGE)                  // 73728 -> 2 CTAs/SM

template <bool HALF_OUT>
__global__ __launch_bounds__(256, 2) void gemm_h_kernel(
    const __half* __restrict__ Ah, const __half* __restrict__ Bh,
    float* __restrict__ C, __half* __restrict__ Ch, int N, int K)
{
    extern __shared__ char smem[];
    const uint32_t sb = cvta_s(smem);

    const int tid = threadIdx.x, warp = tid >> 5, lane = tid & 31;
    const int m0 = blockIdx.x * 128;
    const int n0 = blockIdx.y * 128;

    const int wm = warp >> 1, wn = warp & 1;
    const int la = (lane & 15) * GPAD + ((lane >> 4) << 3);
    const int lb = (((lane >> 4) << 3) + (lane & 7)) * GPAD + (((lane >> 3) & 1) << 3);

    const int nk = K >> 6;  // K / 64

    auto load_stage = [&](int s, int kt) {
        const uint32_t base = sb + s * HSTAGE;
        const int k0 = kt << 6;
#pragma unroll
        for (int t = 0; t < 4; t++) {
            int idx = tid + t * 256;
            int r = idx >> 3, c = idx & 7;
            uint32_t off = (uint32_t)(r * (GPAD * 2) + c * 16);
            cp16(base + off,        Ah + (size_t)(m0 + r) * K + k0 + c * 8);
            cp16(base + HARR + off, Bh + (size_t)(n0 + r) * K + k0 + c * 8);
        }
        asm volatile("cp.async.commit_group;" ::: "memory");
    };

    float acc[2][8][4] = {};
    load_stage(0, 0);

#pragma unroll 1
    for (int kt = 0; kt < nk; kt++) {
        const int cur = kt & 1;
        __syncthreads();
        if (kt + 1 < nk) {
            load_stage(cur ^ 1, kt + 1);
            asm volatile("cp.async.wait_group 1;" ::: "memory");
        } else {
            asm volatile("cp.async.wait_group 0;" ::: "memory");
        }
        __syncthreads();

        const uint32_t bAh = sb + cur * HSTAGE;
        const uint32_t bBh = bAh + HARR;

#pragma unroll
        for (int kk = 0; kk < 4; kk++) {
            uint32_t Afh[2][4];
#pragma unroll
            for (int mi = 0; mi < 2; mi++) {
                uint32_t off = (uint32_t)(((wm * 32 + mi * 16) * GPAD + kk * 16 + la) << 1);
                ldsm4(Afh[mi], bAh + off);
            }
            uint32_t Bfh[8][2];
#pragma unroll
            for (int ni = 0; ni < 4; ni++) {
                uint32_t t4[4];
                uint32_t off = (uint32_t)(((wn * 64 + ni * 16) * GPAD + kk * 16 + lb) << 1);
                ldsm4(t4, bBh + off);
                Bfh[2 * ni][0] = t4[0]; Bfh[2 * ni][1] = t4[1];
                Bfh[2 * ni + 1][0] = t4[2]; Bfh[2 * ni + 1][1] = t4[3];
            }
#pragma unroll
            for (int mi = 0; mi < 2; mi++)
#pragma unroll
                for (int nj = 0; nj < 8; nj++)
                    mma_f16(acc[mi][nj], Afh[mi], Bfh[nj]);
        }
    }

    const int g = lane >> 2, t = lane & 3;
#pragma unroll
    for (int mi = 0; mi < 2; mi++) {
        int r = m0 + wm * 32 + mi * 16 + g;
#pragma unroll
        for (int nj = 0; nj < 8; nj++) {
            int c = n0 + wn * 64 + nj * 8 + t * 2;
            if (HALF_OUT) {
                __stcs(reinterpret_cast<uint32_t*>(Ch + (size_t)r * N + c),
                       pack2h(acc[mi][nj][0], acc[mi][nj][1]));
                __stcs(reinterpret_cast<uint32_t*>(Ch + (size_t)(r + 8) * N + c),
                       pack2h(acc[mi][nj][2], acc[mi][nj][3]));
            } else {
                __stcs(reinterpret_cast<float2*>(C + (size_t)r * N + c),
                       make_float2(acc[mi][nj][0], acc[mi][nj][1]));
                __stcs(reinterpret_cast<float2*>(C + (size_t)(r + 8) * N + c),
                       make_float2(acc[mi][nj][2], acc[mi][nj][3]));
            }
        }
    }
}

// ---------------- flash attention: 128-row q tiles, 2-stage KV -------------
// QK: Qh*Kh (1-term). PV: Ph*Vh (1-term). fp32 online softmax.
#define APAD 136
#define KARR (64 * APAD * 2)
#define ATTN_SMEM ((128 + 4 * 64) * APAD * 2)   // 104448 B

__global__ __launch_bounds__(256) void attn_kernel(const __half* __restrict__ qh,
                                                   __half* __restrict__ ath)
{
    extern __shared__ __half smA[];
    __half* sQh = smA;
    const uint32_t QhB = cvta_s(sQh);
    const uint32_t KVB = cvta_s(sQh + 128 * APAD);

    const int tid = threadIdx.x, lane = tid & 31, warp = tid >> 5;
    const int bq = gridDim.x - 1 - blockIdx.x;    // heavy tiles first
    const int h = blockIdx.y;
    const int q0 = bq * 128;
    const int nkb = 2 * (bq + 1);
    const float slope = (h < 32) ? exp2f(-0.25f * (float)(h + 1))
                                 : exp2f(-0.125f * (float)(2 * (h - 32) + 1));
    const float scale = 0.08838834764831845f;

#pragma unroll
    for (int j = 0; j < 8; j++) {
        int c = tid + j * 256;
        int row = c >> 4, col8 = c & 15;
        uint32_t off = (uint32_t)((row * APAD + col8 * 8) * 2);
        cp16(QhB + off, qh + (size_t)(q0 + row) * QKVN + h * 128 + col8 * 8);
    }

    auto load_kv = [&](int buf, int kb) {
        const uint32_t base = KVB + (uint32_t)buf * (2 * KARR);
#pragma unroll
        for (int j = 0; j < 4; j++) {
            int c = tid + j * 256;
            int row = c >> 4, col8 = c & 15;
            uint32_t off = (uint32_t)((row * APAD + col8 * 8) * 2);
            size_t gk = (size_t)(kb * 64 + row) * QKVN + HID + h * 128 + col8 * 8;
            cp16(base + off,        qh + gk);
            cp16(base + KARR + off, qh + gk + HID);
        }
        asm volatile("cp.async.commit_group;" ::: "memory");
    };

    load_kv(0, 0);

    float m0 = -1e30f, m1 = -1e30f, l0 = 0.f, l1 = 0.f;
    float o[16][4] = {};

    const int qm = warp * 16;
    const int g = lane >> 2, t = lane & 3;
    const int la = (lane & 15) * APAD + ((lane >> 4) << 3);
    const int lb = (((lane >> 4) << 3) + (lane & 7)) * APAD + (((lane >> 3) & 1) << 3);
    const int lv = ((((lane >> 3) & 1) << 3) + (lane & 7)) * APAD + ((lane >> 4) << 3);
    const int qpos0 = q0 + qm + g, qpos1 = qpos0 + 8;

#pragma unroll 1
    for (int kb = 0; kb < nkb; kb++) {
        const int cur = kb & 1;
        __syncthreads();
        if (kb + 1 < nkb) {
            load_kv(cur ^ 1, kb + 1);
            asm volatile("cp.async.wait_group 1;" ::: "memory");
        } else {
            asm volatile("cp.async.wait_group 0;" ::: "memory");
        }
        __syncthreads();

        const uint32_t KhB = KVB + (uint32_t)cur * (2 * KARR);
        const uint32_t VhB = KhB + KARR;

        float sc[8][4];
#pragma unroll
        for (int i = 0; i < 8; i++)
#pragma unroll
            for (int j = 0; j < 4; j++) sc[i][j] = 0.f;

#pragma unroll
        for (int kc = 0; kc < 8; kc++) {
            uint32_t qfh[4];
            ldsm4(qfh, QhB + (uint32_t)((qm * APAD + kc * 16 + la) << 1));
#pragma unroll
            for (int np = 0; np < 4; np++) {
                uint32_t th[4];
                uint32_t off = (uint32_t)(((np * 16) * APAD + kc * 16 + lb) << 1);
                ldsm4(th, KhB + off);
                uint32_t bh0[2] = {th[0], th[1]}, bh1[2] = {th[2], th[3]};
                mma_f16(sc[2 * np],     qfh, bh0);
                mma_f16(sc[2 * np + 1], qfh, bh1);
            }
        }

        float mt0 = -1e30f, mt1 = -1e30f;
#pragma unroll
        for (int nt = 0; nt < 8; nt++) {
#pragma unroll
            for (int c = 0; c < 2; c++) {
                int kv = kb * 64 + nt * 8 + t * 2 + c;
                float s0 = (kv <= qpos0) ? fmaf(sc[nt][c], scale, -slope * (float)(qpos0 - kv)) : -1e30f;
                float s1 = (kv <= qpos1) ? fmaf(sc[nt][2 + c], scale, -slope * (float)(qpos1 - kv)) : -1e30f;
                sc[nt][c] = s0; sc[nt][2 + c] = s1;
                mt0 = fmaxf(mt0, s0); mt1 = fmaxf(mt1, s1);
            }
        }
        mt0 = fmaxf(mt0, __shfl_xor_sync(0xffffffffu, mt0, 1));
        mt0 = fmaxf(mt0, __shfl_xor_sync(0xffffffffu, mt0, 2));
        mt1 = fmaxf(mt1, __shfl_xor_sync(0xffffffffu, mt1, 1));
        mt1 = fmaxf(mt1, __shfl_xor_sync(0xffffffffu, mt1, 2));
        float mn0 = fmaxf(m0, mt0), mn1 = fmaxf(m1, mt1);
        float f0 = __expf(m0 - mn0), f1 = __expf(m1 - mn1);
        m0 = mn0; m1 = mn1;

        float s0 = 0.f, s1 = 0.f;
#pragma unroll
        for (int nt = 0; nt < 8; nt++) {
            float p0 = __expf(sc[nt][0] - m0), p1 = __expf(sc[nt][1] - m0);
            float p2 = __expf(sc[nt][2] - m1), p3 = __expf(sc[nt][3] - m1);
            sc[nt][0] = p0; sc[nt][1] = p1; sc[nt][2] = p2; sc[nt][3] = p3;
            s0 += p0 + p1; s1 += p2 + p3;
        }
        s0 += __shfl_xor_sync(0xffffffffu, s0, 1);
        s0 += __shfl_xor_sync(0xffffffffu, s0, 2);
        s1 += __shfl_xor_sync(0xffffffffu, s1, 1);
        s1 += __shfl_xor_sync(0xffffffffu, s1, 2);
        l0 = l0 * f0 + s0;
        l1 = l1 * f1 + s1;
#pragma unroll
        for (int db = 0; db < 16; db++) {
            o[db][0] *= f0; o[db][1] *= f0; o[db][2] *= f1; o[db][3] *= f1;
        }

#pragma unroll
        for (int kc2 = 0; kc2 < 4; kc2++) {
            uint32_t ph2[4];
            ph2[0] = pack2h(sc[2 * kc2][0],     sc[2 * kc2][1]);
            ph2[1] = pack2h(sc[2 * kc2][2],     sc[2 * kc2][3]);
            ph2[2] = pack2h(sc[2 * kc2 + 1][0], sc[2 * kc2 + 1][1]);
            ph2[3] = pack2h(sc[2 * kc2 + 1][2], sc[2 * kc2 + 1][3]);
#pragma unroll
            for (int d16 = 0; d16 < 8; d16++) {
                uint32_t vh[4];
                uint32_t off = (uint32_t)((kc2 * 16 * APAD + d16 * 16 + lv) << 1);
                ldsm4t(vh, VhB + off);
                uint32_t bh0[2] = {vh[0], vh[1]}, bh1[2] = {vh[2], vh[3]};
                mma_f16(o[2 * d16],     ph2, bh0);
                mma_f16(o[2 * d16 + 1], ph2, bh1);
            }
        }
    }

    float inv0 = 1.f / l0, inv1 = 1.f / l1;
#pragma unroll
    for (int db = 0; db < 16; db++) {
        int col = h * 128 + db * 8 + t * 2;
        int r0 = q0 + qm + g;
        __stcs(reinterpret_cast<uint32_t*>(ath + (size_t)r0 * HID + col),
               pack2h(o[db][0] * inv0, o[db][1] * inv0));
        __stcs(reinterpret_cast<uint32_t*>(ath + (size_t)(r0 + 8) * HID + col),
               pack2h(o[db][2] * inv1, o[db][3] * inv1));
    }
}

// ---------------------------------------------------------------------------
extern "C" void kernel_launch(void* const* d_in, const int* in_sizes, int n_in,
                              void* d_out, int out_size) {
    const float* hs = (const float*)d_in[0];   // [1,2048,5120]
    const float* wp = (const float*)d_in[1];   // [15360,5120]
    const float* wo = (const float*)d_in[2];   // [5120,5120]
    float* out = (float*)d_out;                // [1,2048,5120]

    __half *qkh, *hsh, *wph, *woh, *ath;
    cudaGetSymbolAddress((void**)&qkh, g_qk_h);
    cudaGetSymbolAddress((void**)&hsh, g_hs_h);
    cudaGetSymbolAddress((void**)&wph, g_wp_h);
    cudaGetSymbolAddress((void**)&woh, g_wo_h);
    cudaGetSymbolAddress((void**)&ath, g_at_h);

    // prepasses: fp32 -> fp16
    {
        int n4 = SEQ * HID / 4;
        split_h16_kernel<<<(n4 + 255) / 256, 256>>>((const float4*)hs, (uint2*)hsh, n4);
        n4 = QKVN * HID / 4;
        split_h16_kernel<<<(n4 + 255) / 256, 256>>>((const float4*)wp, (uint2*)wph, n4);
        n4 = HID * HID / 4;
        split_h16_kernel<<<(n4 + 255) / 256, 256>>>((const float4*)wo, (uint2*)woh, n4);
    }

    cudaFuncSetAttribute((const void*)gemm_h_kernel<true>,
                         cudaFuncAttributeMaxDynamicSharedMemorySize, G1_SMEM);
    cudaFuncSetAttribute((const void*)gemm_h_kernel<false>,
                         cudaFuncAttributeMaxDynamicSharedMemorySize, G1_SMEM);
    cudaFuncSetAttribute((const void*)attn_kernel,
                         cudaFuncAttributeMaxDynamicSharedMemorySize, ATTN_SMEM);

    // QKV projection (fp16 1-term, BK=64, 2-stage) -> fp16 [2048,15360]
    gemm_h_kernel<true><<<dim3(SEQ / 128, QKVN / 128), 256, G1_SMEM>>>(
        hsh, wph, nullptr, qkh, QKVN, HID);

    // attention (QK 1-term; PV 1-term; writes fp16)
    attn_kernel<<<dim3(SEQ / 128, 40), 256, ATTN_SMEM>>>(qkh, ath);

    // o_proj (fp16 1-term, BK=64, 2-stage) -> fp32 out
    gemm_h_kernel<false><<<dim3(SEQ / 128, HID / 128), 256, G1_SMEM>>>(
        ath, woh, out, nullptr, HID, HID);
}

// round 16
// speedup vs baseline: 1.5165x; 1.5165x over previous
#include <cuda_runtime.h>
#include <cuda_bf16.h>
#include <cuda_fp16.h>
#include <cstdint>

#define SEQ  2048
#define HID  5120
#define QKVN 15360

// ---------------- scratch (device globals; allocation-free) ----------------
__device__ __align__(256) __half g_qk_h[SEQ * QKVN];   // qkv fp16 (hi only)
__device__ __align__(256) __half g_hs_h[SEQ * HID];
__device__ __align__(256) __half g_wp_h[QKVN * HID];   // w_pack hi only
__device__ __align__(256) __half g_wo_h[HID * HID];    // w_o hi only
__device__ __align__(256) __half g_at_h[SEQ * HID];    // attn out fp16 (hi only)

// ---------------- helpers ----------------
__device__ __forceinline__ uint32_t cvta_s(const void* p) {
    return (uint32_t)__cvta_generic_to_shared(p);
}
__device__ __forceinline__ uint32_t pack2h(float f0, float f1) {
    __half2 v = __floats2half2_rn(f0, f1);
    return *reinterpret_cast<uint32_t*>(&v);
}
__device__ __forceinline__ void ldsm4(uint32_t r[4], uint32_t a) {
    asm volatile("ldmatrix.sync.aligned.m8n8.x4.shared.b16 {%0,%1,%2,%3}, [%4];"
                 : "=r"(r[0]), "=r"(r[1]), "=r"(r[2]), "=r"(r[3]) : "r"(a));
}
__device__ __forceinline__ void ldsm4t(uint32_t r[4], uint32_t a) {
    asm volatile("ldmatrix.sync.aligned.m8n8.x4.trans.shared.b16 {%0,%1,%2,%3}, [%4];"
                 : "=r"(r[0]), "=r"(r[1]), "=r"(r[2]), "=r"(r[3]) : "r"(a));
}
__device__ __forceinline__ void mma_f16(float d[4], const uint32_t a[4], const uint32_t b[2]) {
    asm volatile("mma.sync.aligned.m16n8k16.row.col.f32.f16.f16.f32 "
                 "{%0,%1,%2,%3}, {%4,%5,%6,%7}, {%8,%9}, {%0,%1,%2,%3};"
                 : "+f"(d[0]), "+f"(d[1]), "+f"(d[2]), "+f"(d[3])
                 : "r"(a[0]), "r"(a[1]), "r"(a[2]), "r"(a[3]), "r"(b[0]), "r"(b[1]));
}
__device__ __forceinline__ void cp16(uint32_t dst, const void* src) {
    asm volatile("cp.async.cg.shared.global [%0], [%1], 16;" :: "r"(dst), "l"(src));
}

// ---------------- prepass: fp32 -> fp16 ----------------
__global__ __launch_bounds__(256) void split_h16_kernel(const float4* __restrict__ src,
                                                        uint2* __restrict__ hi, int n4) {
    int i = blockIdx.x * blockDim.x + threadIdx.x;
    if (i >= n4) return;
    float4 v = src[i];
    hi[i] = make_uint2(pack2h(v.x, v.y), pack2h(v.z, v.w));
}

// ---------------- GEMM (fp16, 1-term): C = Ah * Bh^T ------------------------
// BM=128, BN=128, BK=64, 2 stages, 2 CTAs/SM. 8 warps 4(m)x2(n).
// HALF_OUT: write fp16 (Ch); else fp32 (C).
#define GPAD 72
#define HARR (128 * GPAD * 2)                 // 18432 B per array
#define HSTAGE (2 * HARR)                     // 36864
#define G1_SMEM (2 * HSTAGE)                  // 73728 -> 2 CTAs/SM

template <bool HALF_OUT>
__global__ __launch_bounds__(256, 2) void gemm_h_kernel(
    const __half* __restrict__ Ah, const __half* __restrict__ Bh,
    float* __restrict__ C, __half* __restrict__ Ch, int N, int K)
{
    extern __shared__ char smem[];
    const uint32_t sb = cvta_s(smem);

    const int tid = threadIdx.x, warp = tid >> 5, lane = tid & 31;
    const int m0 = blockIdx.x * 128;
    const int n0 = blockIdx.y * 128;

    const int wm = warp >> 1, wn = warp & 1;
    const int la = (lane & 15) * GPAD + ((lane >> 4) << 3);
    const int lb = (((lane >> 4) << 3) + (lane & 7)) * GPAD + (((lane >> 3) & 1) << 3);

    const int nk = K >> 6;  // K / 64

    auto load_stage = [&](int s, int kt) {
        const uint32_t base = sb + s * HSTAGE;
        const int k0 = kt << 6;
#pragma unroll
        for (int t = 0; t < 4; t++) {
            int idx = tid + t * 256;
            int r = idx >> 3, c = idx & 7;
            uint32_t off = (uint32_t)(r * (GPAD * 2) + c * 16);
            cp16(base + off,        Ah + (size_t)(m0 + r) * K + k0 + c * 8);
            cp16(base + HARR + off, Bh + (size_t)(n0 + r) * K + k0 + c * 8);
        }
        asm volatile("cp.async.commit_group;" ::: "memory");
    };

    float acc[2][8][4] = {};
    load_stage(0, 0);

#pragma unroll 1
    for (int kt = 0; kt < nk; kt++) {
        const int cur = kt & 1;
        __syncthreads();
        if (kt + 1 < nk) {
            load_stage(cur ^ 1, kt + 1);
            asm volatile("cp.async.wait_group 1;" ::: "memory");
        } else {
            asm volatile("cp.async.wait_group 0;" ::: "memory");
        }
        __syncthreads();

        const uint32_t bAh = sb + cur * HSTAGE;
        const uint32_t bBh = bAh + HARR;

#pragma unroll
        for (int kk = 0; kk < 4; kk++) {
            uint32_t Afh[2][4];
#pragma unroll
            for (int mi = 0; mi < 2; mi++) {
                uint32_t off = (uint32_t)(((wm * 32 + mi * 16) * GPAD + kk * 16 + la) << 1);
                ldsm4(Afh[mi], bAh + off);
            }
            uint32_t Bfh[8][2];
#pragma unroll
            for (int ni = 0; ni < 4; ni++) {
                uint32_t t4[4];
                uint32_t off = (uint32_t)(((wn * 64 + ni * 16) * GPAD + kk * 16 + lb) << 1);
                ldsm4(t4, bBh + off);
                Bfh[2 * ni][0] = t4[0]; Bfh[2 * ni][1] = t4[1];
                Bfh[2 * ni + 1][0] = t4[2]; Bfh[2 * ni + 1][1] = t4[3];
            }
#pragma unroll
            for (int mi = 0; mi < 2; mi++)
#pragma unroll
                for (int nj = 0; nj < 8; nj++)
                    mma_f16(acc[mi][nj], Afh[mi], Bfh[nj]);
        }
    }

    const int g = lane >> 2, t = lane & 3;
#pragma unroll
    for (int mi = 0; mi < 2; mi++) {
        int r = m0 + wm * 32 + mi * 16 + g;
#pragma unroll
        for (int nj = 0; nj < 8; nj++) {
            int c = n0 + wn * 64 + nj * 8 + t * 2;
            if (HALF_OUT) {
                __stcs(reinterpret_cast<uint32_t*>(Ch + (size_t)r * N + c),
                       pack2h(acc[mi][nj][0], acc[mi][nj][1]));
                __stcs(reinterpret_cast<uint32_t*>(Ch + (size_t)(r + 8) * N + c),
                       pack2h(acc[mi][nj][2], acc[mi][nj][3]));
            } else {
                __stcs(reinterpret_cast<float2*>(C + (size_t)r * N + c),
                       make_float2(acc[mi][nj][0], acc[mi][nj][1]));
                __stcs(reinterpret_cast<float2*>(C + (size_t)(r + 8) * N + c),
                       make_float2(acc[mi][nj][2], acc[mi][nj][3]));
            }
        }
    }
}

// ---------------- flash attention: 128-row q tiles, 2-stage KV -------------
// QK: Qh*Kh (1-term). PV: Ph*Vh (1-term). fp32 online softmax.
#define APAD 136
#define KARR (64 * APAD * 2)
#define ATTN_SMEM ((128 + 4 * 64) * APAD * 2)   // 104448 B

__global__ __launch_bounds__(256) void attn_kernel(const __half* __restrict__ qh,
                                                   __half* __restrict__ ath)
{
    extern __shared__ __half smA[];
    __half* sQh = smA;
    const uint32_t QhB = cvta_s(sQh);
    const uint32_t KVB = cvta_s(sQh + 128 * APAD);

    const int tid = threadIdx.x, lane = tid & 31, warp = tid >> 5;
    const int bq = gridDim.x - 1 - blockIdx.x;    // heavy tiles first
    const int h = blockIdx.y;
    const int q0 = bq * 128;
    const int nkb = 2 * (bq + 1);
    const float slope = (h < 32) ? exp2f(-0.25f * (float)(h + 1))
                                 : exp2f(-0.125f * (float)(2 * (h - 32) + 1));
    const float scale = 0.08838834764831845f;

#pragma unroll
    for (int j = 0; j < 8; j++) {
        int c = tid + j * 256;
        int row = c >> 4, col8 = c & 15;
        uint32_t off = (uint32_t)((row * APAD + col8 * 8) * 2);
        cp16(QhB + off, qh + (size_t)(q0 + row) * QKVN + h * 128 + col8 * 8);
    }

    auto load_kv = [&](int buf, int kb) {
        const uint32_t base = KVB + (uint32_t)buf * (2 * KARR);
#pragma unroll
        for (int j = 0; j < 4; j++) {
            int c = tid + j * 256;
            int row = c >> 4, col8 = c & 15;
            uint32_t off = (uint32_t)((row * APAD + col8 * 8) * 2);
            size_t gk = (size_t)(kb * 64 + row) * QKVN + HID + h * 128 + col8 * 8;
            cp16(base + off,        qh + gk);
            cp16(base + KARR + off, qh + gk + HID);
        }
        asm volatile("cp.async.commit_group;" ::: "memory");
    };

    load_kv(0, 0);

    float m0 = -1e30f, m1 = -1e30f, l0 = 0.f, l1 = 0.f;
    float o[16][4] = {};

    const int qm = warp * 16;
    const int g = lane >> 2, t = lane & 3;
    const int la = (lane & 15) * APAD + ((lane >> 4) << 3);
    const int lb = (((lane >> 4) << 3) + (lane & 7)) * APAD + (((lane >> 3) & 1) << 3);
    const int lv = ((((lane >> 3) & 1) << 3) + (lane & 7)) * APAD + ((lane >> 4) << 3);
    const int qpos0 = q0 + qm + g, qpos1 = qpos0 + 8;

#pragma unroll 1
    for (int kb = 0; kb < nkb; kb++) {
        const int cur = kb & 1;
        __syncthreads();
        if (kb + 1 < nkb) {
            load_kv(cur ^ 1, kb + 1);
            asm volatile("cp.async.wait_group 1;" ::: "memory");
        } else {
            asm volatile("cp.async.wait_group 0;" ::: "memory");
        }
        __syncthreads();

        const uint32_t KhB = KVB + (uint32_t)cur * (2 * KARR);
        const uint32_t VhB = KhB + KARR;

        float sc[8][4];
#pragma unroll
        for (int i = 0; i < 8; i++)
#pragma unroll
            for (int j = 0; j < 4; j++) sc[i][j] = 0.f;

#pragma unroll
        for (int kc = 0; kc < 8; kc++) {
            uint32_t qfh[4];
            ldsm4(qfh, QhB + (uint32_t)((qm * APAD + kc * 16 + la) << 1));
#pragma unroll
            for (int np = 0; np < 4; np++) {
                uint32_t th[4];
                uint32_t off = (uint32_t)(((np * 16) * APAD + kc * 16 + lb) << 1);
                ldsm4(th, KhB + off);
                uint32_t bh0[2] = {th[0], th[1]}, bh1[2] = {th[2], th[3]};
                mma_f16(sc[2 * np],     qfh, bh0);
                mma_f16(sc[2 * np + 1], qfh, bh1);
            }
        }

        float mt0 = -1e30f, mt1 = -1e30f;
#pragma unroll
        for (int nt = 0; nt < 8; nt++) {
#pragma unroll
            for (int c = 0; c < 2; c++) {
                int kv = kb * 64 + nt * 8 + t * 2 + c;
                float s0 = (kv <= qpos0) ? fmaf(sc[nt][c], scale, -slope * (float)(qpos0 - kv)) : -1e30f;
                float s1 = (kv <= qpos1) ? fmaf(sc[nt][2 + c], scale, -slope * (float)(qpos1 - kv)) : -1e30f;
                sc[nt][c] = s0; sc[nt][2 + c] = s1;
                mt0 = fmaxf(mt0, s0); mt1 = fmaxf(mt1, s1);
            }
        }
        mt0 = fmaxf(mt0, __shfl_xor_sync(0xffffffffu, mt0, 1));
        mt0 = fmaxf(mt0, __shfl_xor_sync(0xffffffffu, mt0, 2));
        mt1 = fmaxf(mt1, __shfl_xor_sync(0xffffffffu, mt1, 1));
        mt1 = fmaxf(mt1, __shfl_xor_sync(0xffffffffu, mt1, 2));
        float mn0 = fmaxf(m0, mt0), mn1 = fmaxf(m1, mt1);
        float f0 = __expf(m0 - mn0), f1 = __expf(m1 - mn1);
        m0 = mn0; m1 = mn1;

        float s0 = 0.f, s1 = 0.f;
#pragma unroll
        for (int nt = 0; nt < 8; nt++) {
            float p0 = __expf(sc[nt][0] - m0), p1 = __expf(sc[nt][1] - m0);
            float p2 = __expf(sc[nt][2] - m1), p3 = __expf(sc[nt][3] - m1);
            sc[nt][0] = p0; sc[nt][1] = p1; sc[nt][2] = p2; sc[nt][3] = p3;
            s0 += p0 + p1; s1 += p2 + p3;
        }
        s0 += __shfl_xor_sync(0xffffffffu, s0, 1);
        s0 += __shfl_xor_sync(0xffffffffu, s0, 2);
        s1 += __shfl_xor_sync(0xffffffffu, s1, 1);
        s1 += __shfl_xor_sync(0xffffffffu, s1, 2);
        l0 = l0 * f0 + s0;
        l1 = l1 * f1 + s1;
#pragma unroll
        for (int db = 0; db < 16; db++) {
            o[db][0] *= f0; o[db][1] *= f0; o[db][2] *= f1; o[db][3] *= f1;
        }

#pragma unroll
        for (int kc2 = 0; kc2 < 4; kc2++) {
            uint32_t ph2[4];
            ph2[0] = pack2h(sc[2 * kc2][0],     sc[2 * kc2][1]);
            ph2[1] = pack2h(sc[2 * kc2][2],     sc[2 * kc2][3]);
            ph2[2] = pack2h(sc[2 * kc2 + 1][0], sc[2 * kc2 + 1][1]);
            ph2[3] = pack2h(sc[2 * kc2 + 1][2], sc[2 * kc2 + 1][3]);
#pragma unroll
            for (int d16 = 0; d16 < 8; d16++) {
                uint32_t vh[4];
                uint32_t off = (uint32_t)((kc2 * 16 * APAD + d16 * 16 + lv) << 1);
                ldsm4t(vh, VhB + off);
                uint32_t bh0[2] = {vh[0], vh[1]}, bh1[2] = {vh[2], vh[3]};
                mma_f16(o[2 * d16],     ph2, bh0);
                mma_f16(o[2 * d16 + 1], ph2, bh1);
            }
        }
    }

    float inv0 = 1.f / l0, inv1 = 1.f / l1;
#pragma unroll
    for (int db = 0; db < 16; db++) {
        int col = h * 128 + db * 8 + t * 2;
        int r0 = q0 + qm + g;
        __stcs(reinterpret_cast<uint32_t*>(ath + (size_t)r0 * HID + col),
               pack2h(o[db][0] * inv0, o[db][1] * inv0));
        __stcs(reinterpret_cast<uint32_t*>(ath + (size_t)(r0 + 8) * HID + col),
               pack2h(o[db][2] * inv1, o[db][3] * inv1));
    }
}

// ---------------------------------------------------------------------------
extern "C" void kernel_launch(void* const* d_in, const int* in_sizes, int n_in,
                              void* d_out, int out_size) {
    const float* hs = (const float*)d_in[0];   // [1,2048,5120]
    const float* wp = (const float*)d_in[1];   // [15360,5120]
    const float* wo = (const float*)d_in[2];   // [5120,5120]
    float* out = (float*)d_out;                // [1,2048,5120]

    __half *qkh, *hsh, *wph, *woh, *ath;
    cudaGetSymbolAddress((void**)&qkh, g_qk_h);
    cudaGetSymbolAddress((void**)&hsh, g_hs_h);
    cudaGetSymbolAddress((void**)&wph, g_wp_h);
    cudaGetSymbolAddress((void**)&woh, g_wo_h);
    cudaGetSymbolAddress((void**)&ath, g_at_h);

    // prepasses: fp32 -> fp16
    {
        int n4 = SEQ * HID / 4;
        split_h16_kernel<<<(n4 + 255) / 256, 256>>>((const float4*)hs, (uint2*)hsh, n4);
        n4 = QKVN * HID / 4;
        split_h16_kernel<<<(n4 + 255) / 256, 256>>>((const float4*)wp, (uint2*)wph, n4);
        n4 = HID * HID / 4;
        split_h16_kernel<<<(n4 + 255) / 256, 256>>>((const float4*)wo, (uint2*)woh, n4);
    }

    cudaFuncSetAttribute((const void*)gemm_h_kernel<true>,
                         cudaFuncAttributeMaxDynamicSharedMemorySize, G1_SMEM);
    cudaFuncSetAttribute((const void*)gemm_h_kernel<false>,
                         cudaFuncAttributeMaxDynamicSharedMemorySize, G1_SMEM);
    cudaFuncSetAttribute((const void*)attn_kernel,
                         cudaFuncAttributeMaxDynamicSharedMemorySize, ATTN_SMEM);

    // QKV projection (fp16 1-term, BK=64, 2-stage) -> fp16 [2048,15360]
    gemm_h_kernel<true><<<dim3(SEQ / 128, QKVN / 128), 256, G1_SMEM>>>(
        hsh, wph, nullptr, qkh, QKVN, HID);

    // attention (QK 1-term; PV 1-term; writes fp16)
    attn_kernel<<<dim3(SEQ / 128, 40), 256, ATTN_SMEM>>>(qkh, ath);

    // o_proj (fp16 1-term, BK=64, 2-stage) -> fp32 out
    gemm_h_kernel<false><<<dim3(SEQ / 128, HID / 128), 256, G1_SMEM>>>(
        ath, woh, out, nullptr, HID, HID);
}